// round 1
// baseline (speedup 1.0000x reference)
#include <cuda_runtime.h>
#include <stdint.h>

// Modern JAX (>=0.4.36) defaults jax_threefry_partitionable=True.
// If rel_err comes back O(1), flip this to 0 (legacy counter layout).
#define JAX_PARTITIONABLE 1

#define BSZ   2
#define CH    64
#define FLATN 16384
#define NPTS  2048
#define KSMP  256
#define HID   32

// ---------------- device scratch (no runtime allocation allowed) ------------
__device__ float g_xi    [BSZ*NPTS*CH];
__device__ float g_mpe   [BSZ*NPTS*CH];
__device__ float g_A1    [BSZ*NPTS*HID];
__device__ float g_prob  [BSZ*NPTS];
__device__ float g_logp  [BSZ*NPTS];
__device__ int   g_topk  [BSZ*KSMP];
__device__ float g_B1T   [BSZ*HID*KSMP];   // [b][i][k] transposed for coalesced read
__device__ float g_tf    [BSZ*KSMP*CH];
__device__ float g_nek   [BSZ*KSMP];
__device__ float g_xintra[BSZ*NPTS*CH];
__device__ float g_xinter[BSZ*NPTS*CH];
__device__ float g_Weff  [4*CH*CH];        // w_r1 @ w_r2  (256 x 64)
__device__ float g_Win   [CH*CH];          // Weff[0:64] + Weff[192:256]
__device__ float g_beff  [CH];             // b_r1 @ w_r2 + b_r2
__device__ float g_s1[HID], g_bias1[HID], g_W2T[HID*HID], g_bias2[HID];
__device__ float g_sne[HID], g_biasne[HID];

// ---------------- helpers ----------------------------------------------------
__device__ __forceinline__ float warpsum(float v) {
    #pragma unroll
    for (int o = 16; o > 0; o >>= 1) v += __shfl_xor_sync(0xffffffffu, v, o);
    return v;
}

__device__ __forceinline__ uint32_t rotl32(uint32_t x, int d) {
    return (x << d) | (x >> (32 - d));
}

// JAX threefry2x32 (5 groups of 4 rounds + key injections)
__device__ __forceinline__ void tf2x32(uint32_t k0, uint32_t k1,
                                       uint32_t x0, uint32_t x1,
                                       uint32_t& o0, uint32_t& o1) {
    uint32_t ks0 = k0, ks1 = k1, ks2 = k0 ^ k1 ^ 0x1BD11BDAu;
    x0 += ks0; x1 += ks1;
#define TF_RND(r) { x0 += x1; x1 = rotl32(x1, r); x1 ^= x0; }
    TF_RND(13) TF_RND(15) TF_RND(26) TF_RND(6)  x0 += ks1; x1 += ks2 + 1u;
    TF_RND(17) TF_RND(29) TF_RND(16) TF_RND(24) x0 += ks2; x1 += ks0 + 2u;
    TF_RND(13) TF_RND(15) TF_RND(26) TF_RND(6)  x0 += ks0; x1 += ks1 + 3u;
    TF_RND(17) TF_RND(29) TF_RND(16) TF_RND(24) x0 += ks1; x1 += ks2 + 4u;
    TF_RND(13) TF_RND(15) TF_RND(26) TF_RND(6)  x0 += ks2; x1 += ks0 + 5u;
#undef TF_RND
    o0 = x0; o1 = x1;
}

// ---------------- prep: BN folds, effective biases ---------------------------
__global__ void prep_kernel(const float* b_ne1, const float* g_ne, const float* be_ne,
                            const float* b_p1,  const float* g_p1, const float* be_p1,
                            const float* w_p2,  const float* b_p2, const float* g_p2,
                            const float* be_p2,
                            const float* b_r1,  const float* w_r2, const float* b_r2) {
    int t = threadIdx.x;
    float inv = 1.0f / sqrtf(1.0f + 1e-5f);
    if (t < HID) {
        float sne = g_ne[t] * inv;
        g_sne[t] = sne;
        g_biasne[t] = fmaf(b_ne1[t], sne, be_ne[t]);
        float s1 = g_p1[t] * inv;
        g_s1[t] = s1;
        g_bias1[t] = fmaf(b_p1[t], s1, be_p1[t]);
        float s2 = g_p2[t] * inv;
        g_bias2[t] = fmaf(b_p2[t], s2, be_p2[t]);
        for (int i = 0; i < HID; i++)                 // transposed, scaled W2
            g_W2T[t*HID + i] = w_p2[i*HID + t] * s2;
    }
    if (t < CH) {
        float acc = b_r2[t];
        for (int m = 0; m < 2*CH; m++) acc = fmaf(b_r1[m], w_r2[m*CH + t], acc);
        g_beff[t] = acc;
    }
}

// W_eff = w_r1 (256x128) @ w_r2 (128x64)
__global__ void weff_kernel(const float* w_r1, const float* w_r2) {
    __shared__ float row[2*CH];
    int c = blockIdx.x, f = threadIdx.x;
    row[f]      = w_r1[c*2*CH + f];
    row[f + CH] = w_r1[c*2*CH + f + CH];
    __syncthreads();
    float acc = 0.f;
    #pragma unroll 8
    for (int m = 0; m < 2*CH; m++) acc = fmaf(row[m], w_r2[m*CH + f], acc);
    g_Weff[c*CH + f] = acc;
}

__global__ void win_kernel() {
    int c = blockIdx.x, f = threadIdx.x;
    g_Win[c*CH + f] = g_Weff[c*CH + f] + g_Weff[(3*CH + c)*CH + f];
}

// ---------------- gather masked voxels + positional encoding -----------------
__global__ void gxi_kernel(const float* input, const int* mask_idx) {
    int bn = blockIdx.x;
    int b  = bn / NPTS;
    int c  = threadIdx.x;
    int v  = mask_idx[bn];
    int j  = c >> 1;
    const float kc = -0.1439115683121279f;            // -ln(10000)/64
    float div = expf((float)(2*j) * kc);
    float ang = (float)v * div;
    float pe  = (c & 1) ? cosf(ang) : sinf(ang);
    float xi  = input[(b*CH + c)*FLATN + v] + pe;
    g_xi [bn*CH + c] = xi;
    g_mpe[bn*CH + c] = pe;
}

// ---------------- per-point: ne-prob branch + A1 = (xi@w_p1)*s1 --------------
__global__ void feat_kernel(const float* w_ne1, const float* w_ne2,
                            const float* b_ne2, const float* w_p1) {
    int bn = blockIdx.x;
    int j  = threadIdx.x;
    __shared__ float xs[CH];
    xs[j]      = g_xi[bn*CH + j];
    xs[j + 32] = g_xi[bn*CH + j + 32];
    __syncwarp();
    float dn = 0.f, dp = 0.f;
    #pragma unroll
    for (int c = 0; c < CH; c++) {
        float x = xs[c];
        dn = fmaf(x, w_ne1[c*HID + j], dn);
        dp = fmaf(x, w_p1 [c*HID + j], dp);
    }
    g_A1[bn*HID + j] = dp * g_s1[j];
    float h = fmaxf(fmaf(dn, g_sne[j], g_biasne[j]), 0.f);
    float s = warpsum(h * w_ne2[j]);
    if (j == 0) {
        float logit = s + b_ne2[0];
        float p = 1.f / (1.f + expf(-logit));
        g_prob[bn] = p;
        g_logp[bn] = logf(p);
    }
}

// ---------------- gumbel-max categorical (exact JAX threefry) ----------------
__global__ void sample_kernel() {
    int bi = blockIdx.x;
    int b  = bi / KSMP;
    int i  = bi % KSMP;
    int t  = threadIdx.x;

    uint32_t kb0, kb1;
#if JAX_PARTITIONABLE
    tf2x32(0u, 42u, 0u, (uint32_t)b, kb0, kb1);       // foldlike split
#else
    uint32_t a0, a1, c0, c1;
    tf2x32(0u, 42u, 0u, 2u, a0, a1);
    tf2x32(0u, 42u, 1u, 3u, c0, c1);
    if (b == 0) { kb0 = a0; kb1 = c0; } else { kb0 = a1; kb1 = c1; }
#endif

    const float TINY = 1.1754943508222875e-38f;
    float best = -3.402823466e38f;
    int   bidx = 0x7fffffff;
    for (int n = t; n < NPTS; n += 256) {
        uint32_t m = (uint32_t)(i*NPTS + n);
        uint32_t o0, o1, bits;
#if JAX_PARTITIONABLE
        tf2x32(kb0, kb1, 0u, m, o0, o1);
        bits = o0 ^ o1;
#else
        const uint32_t half = (KSMP * NPTS) / 2;
        if (m < half) { tf2x32(kb0, kb1, m, m + half, o0, o1); bits = o0; }
        else          { tf2x32(kb0, kb1, m - half, m, o0, o1); bits = o1; }
#endif
        float f = __uint_as_float((bits >> 9) | 0x3f800000u) - 1.0f;
        float u = fmaxf(f + TINY, TINY);
        float g = -logf(-logf(u));
        float val = g + g_logp[b*NPTS + n];
        if (val > best) { best = val; bidx = n; }
    }
    __shared__ float sv[256];
    __shared__ int   si[256];
    sv[t] = best; si[t] = bidx;
    __syncthreads();
    for (int s = 128; s > 0; s >>= 1) {
        if (t < s) {
            if (sv[t+s] > sv[t] || (sv[t+s] == sv[t] && si[t+s] < si[t])) {
                sv[t] = sv[t+s]; si[t] = si[t+s];
            }
        }
        __syncthreads();
    }
    if (t == 0) g_topk[bi] = si[0];
}

// ---------------- gather sampled rows: tf, ne_k, B1T = (mpe_k@w_p1)*s1 -------
__global__ void gatherk_kernel(const float* w_p1) {
    int bk = blockIdx.x;
    int b  = bk / KSMP;
    int k  = bk % KSMP;
    int t  = threadIdx.x;
    __shared__ float ms[CH];
    int n   = g_topk[bk];
    int src = (b*NPTS + n)*CH;
    ms[t] = g_mpe[src + t];
    g_tf[bk*CH + t] = g_xi[src + t];
    __syncthreads();
    if (t < HID) {
        float d = 0.f;
        #pragma unroll
        for (int c = 0; c < CH; c++) d = fmaf(ms[c], w_p1[c*HID + t], d);
        g_B1T[(b*HID + t)*KSMP + k] = d * g_s1[t];
    }
    if (t == 0) g_nek[bk] = g_prob[b*NPTS + n];
}

// ---------------- heavy pairwise kernel: one block per (b,n), thread = k -----
__global__ void __launch_bounds__(256) pair_kernel(const float* w_p3, const float* b_p3) {
    int bn = blockIdx.x;
    int b  = bn / NPTS;
    int k  = threadIdx.x;
    __shared__ __align__(16) float W2s[HID*HID];
    __shared__ float A1s[HID], b1s[HID], w3s[HID], b2s[HID];
    __shared__ float wi[KSMP], we[KSMP];
    __shared__ float psI[KSMP], psE[KSMP];
    __shared__ float sums[2];

    if (k < HID) {
        A1s[k] = g_A1[bn*HID + k];
        b1s[k] = g_bias1[k];
        w3s[k] = w_p3[k];
        b2s[k] = g_bias2[k];
    }
    for (int q = k; q < HID*HID; q += 256) W2s[q] = g_W2T[q];
    __syncthreads();

    // layer 1 (decomposed): h1 = relu(A1'[n] + B1'[k] + bias1)
    float h1[HID];
    #pragma unroll
    for (int i = 0; i < HID; i++)
        h1[i] = fmaxf(A1s[i] + g_B1T[(b*HID + i)*KSMP + k] + b1s[i], 0.f);

    // layer 2 (32x32) + layer 3 (32->1)
    float accP = 0.f;
    #pragma unroll
    for (int j = 0; j < HID; j++) {
        float z = b2s[j];
        const float4* wv = reinterpret_cast<const float4*>(&W2s[j*HID]);
        #pragma unroll
        for (int q = 0; q < 8; q++) {
            float4 w = wv[q];
            z = fmaf(h1[4*q+0], w.x, z);
            z = fmaf(h1[4*q+1], w.y, z);
            z = fmaf(h1[4*q+2], w.z, z);
            z = fmaf(h1[4*q+3], w.w, z);
        }
        accP = fmaf(fmaxf(z, 0.f), w3s[j], accP);
    }
    float P  = 1.f / (1.f + expf(-(accP + b_p3[0])));
    float ne = g_nek[b*KSMP + k];
    wi[k] = P * ne;
    we[k] = (1.f - P) * ne;
    __syncthreads();

    // scalar sums of wi / we (two warps)
    if (k < 64) {
        bool isI = (k < 32);
        int  l   = k & 31;
        const float* arr = isI ? wi : we;
        float s = 0.f;
        for (int q = l; q < KSMP; q += 32) s += arr[q];
        s = warpsum(s);
        if (l == 0) sums[isI ? 0 : 1] = s;
    }
    __syncthreads();

    // weighted sums over tf: thread (q,c) handles quarter q, channel c
    {
        int c = k & 63, q = k >> 6;
        float pi = 0.f, pe = 0.f;
        int base = q * 64;
        #pragma unroll 8
        for (int kk = base; kk < base + 64; kk++) {
            float tfv = g_tf[(b*KSMP + kk)*CH + c];
            pi = fmaf(wi[kk], tfv, pi);
            pe = fmaf(we[kk], tfv, pe);
        }
        psI[k] = pi; psE[k] = pe;
    }
    __syncthreads();
    if (k < CH) {
        float si = psI[k] + psI[64 + k] + psI[128 + k] + psI[192 + k];
        float se = psE[k] + psE[64 + k] + psE[128 + k] + psE[192 + k];
        g_xintra[bn*CH + k] = si / sums[0];
        g_xinter[bn*CH + k] = se / sums[1];
    }
}

// ---------------- dense output: out = input @ W_in + beff --------------------
__global__ void __launch_bounds__(256) dense_kernel(const float* input, float* out) {
    __shared__ float X[CH*65];
    __shared__ __align__(16) float Wl[CH*CH];
    __shared__ float bl[CH];
    int b  = blockIdx.y;
    int v0 = blockIdx.x * 64;
    int t  = threadIdx.x;
    for (int q = t; q < CH*64; q += 256) {
        int c = q >> 6, vl = q & 63;
        X[c*65 + vl] = input[(b*CH + c)*FLATN + v0 + vl];
    }
    for (int q = t; q < CH*CH; q += 256) Wl[q] = g_Win[q];
    if (t < CH) bl[t] = g_beff[t];
    __syncthreads();

    int vl = t & 63, fb = (t >> 6) * 16;
    float acc[16];
    #pragma unroll
    for (int i = 0; i < 16; i++) acc[i] = bl[fb + i];
    for (int c = 0; c < CH; c++) {
        float xv = X[c*65 + vl];
        const float4* wr = reinterpret_cast<const float4*>(&Wl[c*CH + fb]);
        #pragma unroll
        for (int r = 0; r < 4; r++) {
            float4 w = wr[r];
            acc[4*r+0] = fmaf(xv, w.x, acc[4*r+0]);
            acc[4*r+1] = fmaf(xv, w.y, acc[4*r+1]);
            acc[4*r+2] = fmaf(xv, w.z, acc[4*r+2]);
            acc[4*r+3] = fmaf(xv, w.w, acc[4*r+3]);
        }
    }
    #pragma unroll
    for (int i = 0; i < 16; i++)
        out[(b*CH + fb + i)*FLATN + v0 + vl] = acc[i];
}

// ---------------- sparse scatter: ctx contribution at masked voxels ----------
__global__ void scatter_kernel(const int* mask_idx, float* out) {
    int bn = blockIdx.x;
    int b  = bn / NPTS;
    int f  = threadIdx.x;
    __shared__ float xa[CH], xb[CH];
    xa[f] = g_xintra[bn*CH + f];
    xb[f] = g_xinter[bn*CH + f];
    __syncthreads();
    int v = mask_idx[bn];
    float acc = 0.f;
    #pragma unroll 4
    for (int j = 0; j < CH; j++) {
        acc = fmaf(xa[j], g_Weff[(CH   + j)*CH + f], acc);
        acc = fmaf(xb[j], g_Weff[(2*CH + j)*CH + f], acc);
    }
    out[(b*CH + f)*FLATN + v] += acc;
}

// -----------------------------------------------------------------------------
extern "C" void kernel_launch(void* const* d_in, const int* in_sizes, int n_in,
                              void* d_out, int out_size) {
    const float* input    = (const float*)d_in[0];
    const int*   mask_idx = (const int*)  d_in[1];
    const float* w_ne1 = (const float*)d_in[2];
    const float* b_ne1 = (const float*)d_in[3];
    const float* g_ne  = (const float*)d_in[4];
    const float* be_ne = (const float*)d_in[5];
    const float* w_ne2 = (const float*)d_in[6];
    const float* b_ne2 = (const float*)d_in[7];
    const float* w_p1  = (const float*)d_in[8];
    const float* b_p1  = (const float*)d_in[9];
    const float* g_p1  = (const float*)d_in[10];
    const float* be_p1 = (const float*)d_in[11];
    const float* w_p2  = (const float*)d_in[12];
    const float* b_p2  = (const float*)d_in[13];
    const float* g_p2  = (const float*)d_in[14];
    const float* be_p2 = (const float*)d_in[15];
    const float* w_p3  = (const float*)d_in[16];
    const float* b_p3  = (const float*)d_in[17];
    const float* w_r1  = (const float*)d_in[18];
    const float* b_r1  = (const float*)d_in[19];
    const float* w_r2  = (const float*)d_in[20];
    const float* b_r2  = (const float*)d_in[21];
    float* out = (float*)d_out;

    prep_kernel<<<1, 64>>>(b_ne1, g_ne, be_ne, b_p1, g_p1, be_p1,
                           w_p2, b_p2, g_p2, be_p2, b_r1, w_r2, b_r2);
    weff_kernel<<<4*CH, CH>>>(w_r1, w_r2);
    win_kernel <<<CH, CH>>>();
    gxi_kernel <<<BSZ*NPTS, CH>>>(input, mask_idx);
    feat_kernel<<<BSZ*NPTS, 32>>>(w_ne1, w_ne2, b_ne2, w_p1);
    sample_kernel<<<BSZ*KSMP, 256>>>();
    gatherk_kernel<<<BSZ*KSMP, CH>>>(w_p1);
    pair_kernel<<<BSZ*NPTS, 256>>>(w_p3, b_p3);
    dense_kernel<<<dim3(FLATN/64, BSZ), 256>>>(input, out);
    scatter_kernel<<<BSZ*NPTS, CH>>>(mask_idx, out);
}